// round 10
// baseline (speedup 1.0000x reference)
#include <cuda_runtime.h>
#include <cuda_fp16.h>
#include <cstdint>

// ---------------------------------------------------------------------------
// out[8192,4096] = x[8192,4096]_fp32 @ sign(fp16(w[4096,4096]))
//
// R10: R7 pipeline (the measured HMMA instruction wall, ~701us GEMM) with the
// x fp32->fp16 conversion FOLDED INTO the GEMM producer path:
//   A: LDG.128 fp32 -> cvt half2 (in MMA shadow) -> STS.128 swizzled
//   B: cp.async (unchanged)
// FULL barrier = 2*THREADS arrivals (noinc cp.async arrive + post-STS arrive).
// Eliminates the 31us cvt_x kernel and its 192MB of HBM traffic.
// ---------------------------------------------------------------------------

#define M_DIM 8192
#define N_DIM 4096
#define K_DIM 4096

#define BM 128
#define BN 256
#define BK 64
#define STAGES 4
#define THREADS 512
#define NKI (K_DIM / BK)   // 64

#define A_TILE_BYTES (BM * BK * 2)            // 16384
#define B_TILE_BYTES (BN * BK * 2)            // 32768
#define STAGE_BYTES  (A_TILE_BYTES + B_TILE_BYTES)   // 49152
#define SMEM_DYN     (1024 + 1024 + STAGES * STAGE_BYTES)  // 198656

// ------------------------------ scratch -----------------------------------
__device__ __align__(1024) __half g_wbt[(size_t)N_DIM * K_DIM];  // 32 MB

// --------------------------- convert kernel --------------------------------
// w[K,N] fp32 -> wbt[N,K] fp16 with value sign(fp16(w)) (sign(0) = 0)
__global__ void cvt_w_kernel(const float* __restrict__ w, __half* __restrict__ wbt) {
    __shared__ __half tile[32][33];
    int n0 = blockIdx.x * 32;
    int k0 = blockIdx.y * 32;
    int tx = threadIdx.x, ty = threadIdx.y;
    #pragma unroll
    for (int j = ty; j < 32; j += 8) {
        float v = w[(size_t)(k0 + j) * N_DIM + n0 + tx];
        float hf = __half2float(__float2half_rn(v));  // exact fp16 round trip
        float s = (hf > 0.f) ? 1.f : ((hf < 0.f) ? -1.f : 0.f);
        tile[j][tx] = __float2half_rn(s);
    }
    __syncthreads();
    #pragma unroll
    for (int j = ty; j < 32; j += 8) {
        wbt[(size_t)(n0 + j) * K_DIM + k0 + tx] = tile[tx][j];
    }
}

// dummy launch: keeps ncu's "-s 5 -c 1" window on the GEMM (period 3:
// 5 mod 3 = 2 = gemm position)
__global__ void prof_pad_kernel() {}

// ------------------------------ PTX helpers -------------------------------
__device__ __forceinline__ uint32_t smem_u32(const void* p) {
    uint32_t a;
    asm("{ .reg .u64 t; cvta.to.shared.u64 t, %1; cvt.u32.u64 %0, t; }"
        : "=r"(a) : "l"(p));
    return a;
}

__device__ __forceinline__ void cp_async_16(uint32_t smem_dst, const void* gmem_src) {
    asm volatile("cp.async.cg.shared.global [%0], [%1], 16;"
                 :: "r"(smem_dst), "l"(gmem_src));
}

#define MBARRIER_INIT(addr, count) \
    asm volatile("mbarrier.init.shared.b64 [%0], %1;" \
                 :: "r"((uint32_t)(addr)), "r"((uint32_t)(count)) : "memory")

#define MBARRIER_ARRIVE(addr) \
    asm volatile("mbarrier.arrive.shared.b64 _, [%0];" \
                 :: "r"((uint32_t)(addr)) : "memory")

#define CPASYNC_MBAR_ARRIVE_NOINC(addr) \
    asm volatile("cp.async.mbarrier.arrive.noinc.shared.b64 [%0];" \
                 :: "r"((uint32_t)(addr)) : "memory")

#define MBARRIER_WAIT_PARITY(mbar_smem_addr, phase_parity) do { \
    uint32_t _mbar = (uint32_t)(mbar_smem_addr); \
    uint32_t _parity = (uint32_t)(phase_parity); \
    uint32_t _done; \
    asm volatile( \
        "{\n\t.reg .pred p;\n\t" \
        "mbarrier.try_wait.parity.acquire.cta.shared::cta.b64 p, [%1], %2;\n\t" \
        "selp.b32 %0, 1, 0, p;\n\t}" \
        : "=r"(_done) : "r"(_mbar), "r"(_parity) : "memory"); \
    if (!_done) { \
        asm volatile( \
            "{\n\t.reg .pred P1;\n\t" \
            "WAIT_LOOP_%=:\n\t" \
            "mbarrier.try_wait.parity.acquire.cta.shared::cta.b64 P1, [%0], %1, 0x989680;\n\t" \
            "@P1 bra.uni WAIT_DONE_%=;\n\t" \
            "bra.uni WAIT_LOOP_%=;\n\t" \
            "WAIT_DONE_%=:\n\t}" \
            :: "r"(_mbar), "r"(_parity) : "memory"); \
    } \
} while(0)

__device__ __forceinline__ void ldmatrix_x4(uint32_t& r0, uint32_t& r1,
                                            uint32_t& r2, uint32_t& r3, uint32_t addr) {
    asm volatile("ldmatrix.sync.aligned.m8n8.x4.shared.b16 {%0,%1,%2,%3}, [%4];"
                 : "=r"(r0), "=r"(r1), "=r"(r2), "=r"(r3) : "r"(addr));
}

__device__ __forceinline__ void mma_16816(float* c, const uint32_t* a, const uint32_t* b) {
    asm volatile(
        "mma.sync.aligned.m16n8k16.row.col.f32.f16.f16.f32 "
        "{%0,%1,%2,%3}, {%4,%5,%6,%7}, {%8,%9}, {%0,%1,%2,%3};"
        : "+f"(c[0]), "+f"(c[1]), "+f"(c[2]), "+f"(c[3])
        : "r"(a[0]), "r"(a[1]), "r"(a[2]), "r"(a[3]), "r"(b[0]), "r"(b[1]));
}

__device__ __forceinline__ void sts128(uint32_t addr, uint32_t r0, uint32_t r1,
                                       uint32_t r2, uint32_t r3) {
    asm volatile("st.shared.v4.b32 [%0], {%1,%2,%3,%4};"
                 :: "r"(addr), "r"(r0), "r"(r1), "r"(r2), "r"(r3) : "memory");
}

// swizzle within a [rows][BK] fp16 tile, 128B rows: 16B chunk XOR (row & 7)
__device__ __forceinline__ uint32_t tile_off(int row, int chunk) {
    return (uint32_t)(row * 128 + ((chunk ^ (row & 7)) << 4));
}

// ------------------------------ GEMM kernel --------------------------------
__global__ void __launch_bounds__(THREADS, 1) bgemm_mma_kernel(
    const float*  __restrict__ X,   // [M,K] fp32 (converted in-kernel)
    const __half* __restrict__ B,   // [N,K] fp16
    float* __restrict__ out)
{
    extern __shared__ uint8_t smem_raw[];
    uint32_t raw = smem_u32(smem_raw);
    const uint32_t hdr   = (raw + 1023u) & ~1023u;
    const uint32_t tiles = hdr + 1024u;

    #define FULL_BAR(s)  (hdr + (uint32_t)(s) * 8u)
    #define EMPTY_BAR(s) (hdr + 64u + (uint32_t)(s) * 8u)

    const int tid  = threadIdx.x;
    const int wid  = tid >> 5;
    const int lane = tid & 31;
    const int m0 = blockIdx.x * BM;
    const int n0 = blockIdx.y * BN;

    const int warp_m = wid & 3;   // 4 warps over M: 32 rows each
    const int warp_n = wid >> 2;  // 4 warps over N: 64 cols each

    // B cp.async mapping: 512 threads x 16B, 256 rows x 8 chunks, 4 passes
    const int ld_row0  = tid >> 3;   // 0..63
    const int ld_chunk = tid & 7;    // 0..7

    // A producer mapping: thread t -> row t>>2, quarter (t&3)*16 fp32 cols
    const int a_row = tid >> 2;      // 0..127
    const int a_cq  = tid & 3;       // 0..3 (16 fp32 each)
    const float4* a_src_base =
        reinterpret_cast<const float4*>(X + (size_t)(m0 + a_row) * K_DIM) + a_cq * 4;
    const uint32_t a_sts0 = tile_off(a_row, a_cq * 2);
    const uint32_t a_sts1 = tile_off(a_row, a_cq * 2 + 1);

    // B load: issue cp.asyncs + noinc arrive
    auto load_B = [&](int slot, int kt) {
        const uint32_t sB = tiles + slot * STAGE_BYTES + A_TILE_BYTES;
        const int kcol = kt * BK + ld_chunk * 8;
        #pragma unroll
        for (int p = 0; p < 4; p++) {
            int row = ld_row0 + p * 64;
            cp_async_16(sB + tile_off(row, ld_chunk),
                        B + (size_t)(n0 + row) * K_DIM + kcol);
        }
        CPASYNC_MBAR_ARRIVE_NOINC(FULL_BAR(slot));
    };

    // A load: fp32 LDG -> half2 regs (returns 8 packed half2)
    auto load_A_regs = [&](int kt, uint32_t h[8]) {
        const float4* src = a_src_base + kt * (BK / 4);
        #pragma unroll
        for (int j = 0; j < 4; j++) {
            float4 v = src[j];
            __half2 h0 = __floats2half2_rn(v.x, v.y);
            __half2 h1 = __floats2half2_rn(v.z, v.w);
            h[j * 2 + 0] = *reinterpret_cast<uint32_t*>(&h0);
            h[j * 2 + 1] = *reinterpret_cast<uint32_t*>(&h1);
        }
    };

    // A store: 2x STS.128 into swizzled tile + release arrive
    auto store_A = [&](int slot, const uint32_t h[8]) {
        const uint32_t sA = tiles + slot * STAGE_BYTES;
        sts128(sA + a_sts0, h[0], h[1], h[2], h[3]);
        sts128(sA + a_sts1, h[4], h[5], h[6], h[7]);
        MBARRIER_ARRIVE(FULL_BAR(slot));   // release: orders the STS
    };

    if (tid == 0) {
        #pragma unroll
        for (int s = 0; s < STAGES; s++) {
            MBARRIER_INIT(FULL_BAR(s), 2 * THREADS);  // noinc + post-STS arrive
            MBARRIER_INIT(EMPTY_BAR(s), THREADS);
        }
        asm volatile("fence.proxy.async.shared::cta;" ::: "memory");
    }
    __syncthreads();

    const int lrow = lane & 15;
    const int lsel = lane >> 4;

    uint32_t a_off[2], b_off[4];
    #pragma unroll
    for (int mi = 0; mi < 2; mi++)
        a_off[mi] = tile_off(warp_m * 32 + mi * 16 + lrow, lsel);
    #pragma unroll
    for (int nj = 0; nj < 4; nj++)
        b_off[nj] = tile_off(warp_n * 64 + nj * 16 + lrow, lsel);

    float acc[2][8][4];
    #pragma unroll
    for (int mi = 0; mi < 2; mi++)
        #pragma unroll
        for (int ni = 0; ni < 8; ni++)
            #pragma unroll
            for (int j = 0; j < 4; j++) acc[mi][ni][j] = 0.f;

    // prologue: fill stages 0..2
    #pragma unroll
    for (int s = 0; s < STAGES - 1; s++) {
        MBARRIER_WAIT_PARITY(EMPTY_BAR(s), 1);
        uint32_t h[8];
        load_A_regs(s, h);
        load_B(s, s);
        store_A(s, h);
    }

    for (int it = 0; it < NKI; it++) {
        const int s = it & 3;
        const uint32_t sA = tiles + s * STAGE_BYTES;
        const uint32_t sB = sA + A_TILE_BYTES;

        MBARRIER_WAIT_PARITY(FULL_BAR(s), (it >> 2) & 1);

        // producer front half: issue loads for stage it+3 (LDG latency hides
        // behind the kk MMA phases below)
        const int kt = it + STAGES - 1;
        const int ps = kt & 3;
        uint32_t h[8];
        if (kt < NKI) {
            MBARRIER_WAIT_PARITY(EMPTY_BAR(ps), ((kt >> 2) & 1) ^ 1);
            load_A_regs(kt, h);
            load_B(ps, kt);
        }

        #pragma unroll
        for (int kk = 0; kk < BK / 16; kk++) {
            const uint32_t kx = (uint32_t)kk << 5;

            uint32_t a[2][4];
            #pragma unroll
            for (int mi = 0; mi < 2; mi++)
                ldmatrix_x4(a[mi][0], a[mi][1], a[mi][2], a[mi][3],
                            (sA + a_off[mi]) ^ kx);
            uint32_t b[8][2];
            #pragma unroll
            for (int nj = 0; nj < 4; nj++) {
                uint32_t r0, r1, r2, r3;
                ldmatrix_x4(r0, r1, r2, r3, (sB + b_off[nj]) ^ kx);
                b[nj * 2 + 0][0] = r0; b[nj * 2 + 1][0] = r1;
                b[nj * 2 + 0][1] = r2; b[nj * 2 + 1][1] = r3;
            }

            if (kk == BK / 16 - 1) MBARRIER_ARRIVE(EMPTY_BAR(s));

            #pragma unroll
            for (int mi = 0; mi < 2; mi++)
                #pragma unroll
                for (int ni = 0; ni < 8; ni++)
                    mma_16816(acc[mi][ni], a[mi], b[ni]);
        }

        // producer back half: commit A into smem and arrive
        if (kt < NKI) store_A(ps, h);
    }

    // ------------------------------ epilogue -------------------------------
    const int tq = lane >> 2;
    const int tp = lane & 3;
    #pragma unroll
    for (int mi = 0; mi < 2; mi++) {
        #pragma unroll
        for (int ni = 0; ni < 8; ni++) {
            int r = m0 + warp_m * 32 + mi * 16 + tq;
            int c = n0 + warp_n * 64 + ni * 8 + tp * 2;
            float2 v0 = make_float2(acc[mi][ni][0], acc[mi][ni][1]);
            float2 v1 = make_float2(acc[mi][ni][2], acc[mi][ni][3]);
            *reinterpret_cast<float2*>(out + (size_t)r * N_DIM + c) = v0;
            *reinterpret_cast<float2*>(out + (size_t)(r + 8) * N_DIM + c) = v1;
        }
    }
}

// ------------------------------- host side --------------------------------
extern "C" void kernel_launch(void* const* d_in, const int* in_sizes, int n_in,
                              void* d_out, int out_size)
{
    const float* x = (const float*)d_in[0];
    const float* w = (const float*)d_in[1];
    float* out = (float*)d_out;

    void* wbt_ptr = nullptr;
    cudaGetSymbolAddress(&wbt_ptr, g_wbt);

    {
        dim3 gw(N_DIM / 32, K_DIM / 32), bw(32, 8);
        cvt_w_kernel<<<gw, bw>>>(w, (__half*)wbt_ptr);
    }

    // pad launch so ncu's "-s 5 -c 1" window lands on the GEMM
    prof_pad_kernel<<<1, 32>>>();

    cudaFuncSetAttribute(bgemm_mma_kernel,
                         cudaFuncAttributeMaxDynamicSharedMemorySize, SMEM_DYN);

    dim3 grid(M_DIM / BM, N_DIM / BN);  // (64, 16)
    bgemm_mma_kernel<<<grid, THREADS, SMEM_DYN>>>(
        x, (const __half*)wbt_ptr, out);
}

// round 11
// speedup vs baseline: 1.4554x; 1.4554x over previous
#include <cuda_runtime.h>
#include <cuda_fp16.h>
#include <cstdint>

// ---------------------------------------------------------------------------
// out[8192,4096] = x[8192,4096]_fp32 @ sign(fp16(w[4096,4096]))
//
// R11: GEMM = R7 exactly (measured legacy-HMMA instruction wall, ~701us).
// Optimized converts:
//   cvt_x: 8 floats/thread, 16B stores            (31 -> ~27us)
//   cvt_w: 64x64 tiles, float4 loads, smem transpose, uint4 stores (34 -> ~15us)
// ---------------------------------------------------------------------------

#define M_DIM 8192
#define N_DIM 4096
#define K_DIM 4096

#define BM 128
#define BN 256
#define BK 64
#define STAGES 4
#define THREADS 512
#define NKI (K_DIM / BK)   // 64

#define A_TILE_BYTES (BM * BK * 2)            // 16384
#define B_TILE_BYTES (BN * BK * 2)            // 32768
#define STAGE_BYTES  (A_TILE_BYTES + B_TILE_BYTES)   // 49152
#define SMEM_DYN     (1024 + 1024 + STAGES * STAGE_BYTES)  // 198656

// ------------------------------ scratch -----------------------------------
__device__ __align__(1024) __half g_xh[(size_t)M_DIM * K_DIM];   // 64 MB
__device__ __align__(1024) __half g_wbt[(size_t)N_DIM * K_DIM];  // 32 MB

// --------------------------- convert kernels -------------------------------
// x fp32 -> fp16, 8 elements per thread, 16B stores
__global__ void __launch_bounds__(256, 8) cvt_x_kernel(
    const float4* __restrict__ x, uint4* __restrict__ xh, int n8)
{
    int i = blockIdx.x * blockDim.x + threadIdx.x;
    if (i >= n8) return;
    float4 v0 = x[i * 2];
    float4 v1 = x[i * 2 + 1];
    __half2 a = __floats2half2_rn(v0.x, v0.y);
    __half2 b = __floats2half2_rn(v0.z, v0.w);
    __half2 c = __floats2half2_rn(v1.x, v1.y);
    __half2 d = __floats2half2_rn(v1.z, v1.w);
    uint4 o;
    o.x = *reinterpret_cast<uint32_t*>(&a);
    o.y = *reinterpret_cast<uint32_t*>(&b);
    o.z = *reinterpret_cast<uint32_t*>(&c);
    o.w = *reinterpret_cast<uint32_t*>(&d);
    xh[i] = o;
}

// w[K,N] fp32 -> wbt[N,K] fp16 sign(fp16(w)); 64x64 tiles, vectorized IO.
// Load: each thread reads float4 (4 consecutive n), writes transposed halves
// into padded smem. Store: each thread writes uint4 = 8 consecutive k.
__global__ void __launch_bounds__(256, 4) cvt_w_kernel(
    const float* __restrict__ w, __half* __restrict__ wbt)
{
    __shared__ __half t[64][72];   // [n][k], padded row (144B) vs 128B stride
    const int n0 = blockIdx.x * 64;
    const int k0 = blockIdx.y * 64;
    const int tid = threadIdx.x;

    // load: 64 k-rows x 16 float4 = 1024 float4; 256 threads x 4
    const int lk = tid >> 4;          // 0..15 (k row base, 4 iters of +16)
    const int ln = (tid & 15) << 2;   // n offset 0..60
    #pragma unroll
    for (int i = 0; i < 4; i++) {
        int k = lk + i * 16;
        float4 v = *reinterpret_cast<const float4*>(
            w + (size_t)(k0 + k) * N_DIM + n0 + ln);
        float f[4] = {v.x, v.y, v.z, v.w};
        #pragma unroll
        for (int j = 0; j < 4; j++) {
            float hf = __half2float(__float2half_rn(f[j]));
            float s = (hf > 0.f) ? 1.f : ((hf < 0.f) ? -1.f : 0.f);
            t[ln + j][k] = __float2half_rn(s);
        }
    }
    __syncthreads();

    // store: 64 n-rows x 8 uint4 = 512 stores; 256 threads x 2
    const int sn = tid >> 2;          // 0..63
    const int sk = (tid & 3) << 3;    // 0,8,16,24
    #pragma unroll
    for (int i = 0; i < 2; i++) {
        int kk = sk + i * 32;
        uint4 o = *reinterpret_cast<uint4*>(&t[sn][kk]);
        *reinterpret_cast<uint4*>(
            wbt + (size_t)(n0 + sn) * K_DIM + k0 + kk) = o;
    }
}

// dummy launch: keeps ncu's "-s 5 -c 1" window on the GEMM (period-4 layout
// proven in R4/R5: index 5 -> position 3 = GEMM)
__global__ void prof_pad_kernel() {}

// ------------------------------ PTX helpers -------------------------------
__device__ __forceinline__ uint32_t smem_u32(const void* p) {
    uint32_t a;
    asm("{ .reg .u64 t; cvta.to.shared.u64 t, %1; cvt.u32.u64 %0, t; }"
        : "=r"(a) : "l"(p));
    return a;
}

__device__ __forceinline__ void cp_async_16(uint32_t smem_dst, const void* gmem_src) {
    asm volatile("cp.async.cg.shared.global [%0], [%1], 16;"
                 :: "r"(smem_dst), "l"(gmem_src));
}

#define MBARRIER_INIT(addr, count) \
    asm volatile("mbarrier.init.shared.b64 [%0], %1;" \
                 :: "r"((uint32_t)(addr)), "r"((uint32_t)(count)) : "memory")

#define MBARRIER_ARRIVE(addr) \
    asm volatile("mbarrier.arrive.shared.b64 _, [%0];" \
                 :: "r"((uint32_t)(addr)) : "memory")

#define CPASYNC_MBAR_ARRIVE_NOINC(addr) \
    asm volatile("cp.async.mbarrier.arrive.noinc.shared.b64 [%0];" \
                 :: "r"((uint32_t)(addr)) : "memory")

#define MBARRIER_WAIT_PARITY(mbar_smem_addr, phase_parity) do { \
    uint32_t _mbar = (uint32_t)(mbar_smem_addr); \
    uint32_t _parity = (uint32_t)(phase_parity); \
    uint32_t _done; \
    asm volatile( \
        "{\n\t.reg .pred p;\n\t" \
        "mbarrier.try_wait.parity.acquire.cta.shared::cta.b64 p, [%1], %2;\n\t" \
        "selp.b32 %0, 1, 0, p;\n\t}" \
        : "=r"(_done) : "r"(_mbar), "r"(_parity) : "memory"); \
    if (!_done) { \
        asm volatile( \
            "{\n\t.reg .pred P1;\n\t" \
            "WAIT_LOOP_%=:\n\t" \
            "mbarrier.try_wait.parity.acquire.cta.shared::cta.b64 P1, [%0], %1, 0x989680;\n\t" \
            "@P1 bra.uni WAIT_DONE_%=;\n\t" \
            "bra.uni WAIT_LOOP_%=;\n\t" \
            "WAIT_DONE_%=:\n\t}" \
            :: "r"(_mbar), "r"(_parity) : "memory"); \
    } \
} while(0)

__device__ __forceinline__ void ldmatrix_x4(uint32_t& r0, uint32_t& r1,
                                            uint32_t& r2, uint32_t& r3, uint32_t addr) {
    asm volatile("ldmatrix.sync.aligned.m8n8.x4.shared.b16 {%0,%1,%2,%3}, [%4];"
                 : "=r"(r0), "=r"(r1), "=r"(r2), "=r"(r3) : "r"(addr));
}

__device__ __forceinline__ void mma_16816(float* c, const uint32_t* a, const uint32_t* b) {
    asm volatile(
        "mma.sync.aligned.m16n8k16.row.col.f32.f16.f16.f32 "
        "{%0,%1,%2,%3}, {%4,%5,%6,%7}, {%8,%9}, {%0,%1,%2,%3};"
        : "+f"(c[0]), "+f"(c[1]), "+f"(c[2]), "+f"(c[3])
        : "r"(a[0]), "r"(a[1]), "r"(a[2]), "r"(a[3]), "r"(b[0]), "r"(b[1]));
}

// swizzle within a [rows][BK] fp16 tile, 128B rows: 16B chunk XOR (row & 7)
__device__ __forceinline__ uint32_t tile_off(int row, int chunk) {
    return (uint32_t)(row * 128 + ((chunk ^ (row & 7)) << 4));
}

// ------------------------------ GEMM kernel (R7) ---------------------------
__global__ void __launch_bounds__(THREADS, 1) bgemm_mma_kernel(
    const __half* __restrict__ A,   // [M,K]
    const __half* __restrict__ B,   // [N,K]
    float* __restrict__ out)
{
    extern __shared__ uint8_t smem_raw[];
    uint32_t raw = smem_u32(smem_raw);
    const uint32_t hdr   = (raw + 1023u) & ~1023u;
    const uint32_t tiles = hdr + 1024u;

    #define FULL_BAR(s)  (hdr + (uint32_t)(s) * 8u)
    #define EMPTY_BAR(s) (hdr + 64u + (uint32_t)(s) * 8u)

    const int tid  = threadIdx.x;
    const int wid  = tid >> 5;
    const int lane = tid & 31;
    const int m0 = blockIdx.x * BM;
    const int n0 = blockIdx.y * BN;

    const int warp_m = wid & 3;   // 4 warps over M: 32 rows each
    const int warp_n = wid >> 2;  // 4 warps over N: 64 cols each

    const int ld_row0  = tid >> 3;   // 0..63
    const int ld_chunk = tid & 7;    // 0..7

    auto load_stage = [&](int slot, int kt) {
        const uint32_t sA = tiles + slot * STAGE_BYTES;
        const uint32_t sB = sA + A_TILE_BYTES;
        const int kcol = kt * BK + ld_chunk * 8;
        #pragma unroll
        for (int p = 0; p < 2; p++) {
            int row = ld_row0 + p * 64;
            cp_async_16(sA + tile_off(row, ld_chunk),
                        A + (size_t)(m0 + row) * K_DIM + kcol);
        }
        #pragma unroll
        for (int p = 0; p < 4; p++) {
            int row = ld_row0 + p * 64;
            cp_async_16(sB + tile_off(row, ld_chunk),
                        B + (size_t)(n0 + row) * K_DIM + kcol);
        }
        CPASYNC_MBAR_ARRIVE_NOINC(FULL_BAR(slot));
    };

    if (tid == 0) {
        #pragma unroll
        for (int s = 0; s < STAGES; s++) {
            MBARRIER_INIT(FULL_BAR(s), THREADS);
            MBARRIER_INIT(EMPTY_BAR(s), THREADS);
        }
        asm volatile("fence.proxy.async.shared::cta;" ::: "memory");
    }
    __syncthreads();

    const int lrow = lane & 15;
    const int lsel = lane >> 4;

    uint32_t a_off[2], b_off[4];
    #pragma unroll
    for (int mi = 0; mi < 2; mi++)
        a_off[mi] = tile_off(warp_m * 32 + mi * 16 + lrow, lsel);
    #pragma unroll
    for (int nj = 0; nj < 4; nj++)
        b_off[nj] = tile_off(warp_n * 64 + nj * 16 + lrow, lsel);

    float acc[2][8][4];
    #pragma unroll
    for (int mi = 0; mi < 2; mi++)
        #pragma unroll
        for (int ni = 0; ni < 8; ni++)
            #pragma unroll
            for (int j = 0; j < 4; j++) acc[mi][ni][j] = 0.f;

    #pragma unroll
    for (int s = 0; s < STAGES - 1; s++) {
        MBARRIER_WAIT_PARITY(EMPTY_BAR(s), 1);
        load_stage(s, s);
    }

    for (int it = 0; it < NKI; it++) {
        const int s = it & 3;
        const uint32_t sA = tiles + s * STAGE_BYTES;
        const uint32_t sB = sA + A_TILE_BYTES;

        MBARRIER_WAIT_PARITY(FULL_BAR(s), (it >> 2) & 1);

        #pragma unroll
        for (int kk = 0; kk < BK / 16; kk++) {
            const uint32_t kx = (uint32_t)kk << 5;

            uint32_t a[2][4];
            #pragma unroll
            for (int mi = 0; mi < 2; mi++)
                ldmatrix_x4(a[mi][0], a[mi][1], a[mi][2], a[mi][3],
                            (sA + a_off[mi]) ^ kx);
            uint32_t b[8][2];
            #pragma unroll
            for (int nj = 0; nj < 4; nj++) {
                uint32_t r0, r1, r2, r3;
                ldmatrix_x4(r0, r1, r2, r3, (sB + b_off[nj]) ^ kx);
                b[nj * 2 + 0][0] = r0; b[nj * 2 + 1][0] = r1;
                b[nj * 2 + 0][1] = r2; b[nj * 2 + 1][1] = r3;
            }

            if (kk == BK / 16 - 1) MBARRIER_ARRIVE(EMPTY_BAR(s));

            #pragma unroll
            for (int mi = 0; mi < 2; mi++)
                #pragma unroll
                for (int ni = 0; ni < 8; ni++)
                    mma_16816(acc[mi][ni], a[mi], b[ni]);
        }

        const int kt = it + STAGES - 1;
        if (kt < NKI) {
            const int ps = kt & 3;
            MBARRIER_WAIT_PARITY(EMPTY_BAR(ps), ((kt >> 2) & 1) ^ 1);
            load_stage(ps, kt);
        }
    }

    // ------------------------------ epilogue -------------------------------
    const int tq = lane >> 2;
    const int tp = lane & 3;
    #pragma unroll
    for (int mi = 0; mi < 2; mi++) {
        #pragma unroll
        for (int ni = 0; ni < 8; ni++) {
            int r = m0 + warp_m * 32 + mi * 16 + tq;
            int c = n0 + warp_n * 64 + ni * 8 + tp * 2;
            float2 v0 = make_float2(acc[mi][ni][0], acc[mi][ni][1]);
            float2 v1 = make_float2(acc[mi][ni][2], acc[mi][ni][3]);
            *reinterpret_cast<float2*>(out + (size_t)r * N_DIM + c) = v0;
            *reinterpret_cast<float2*>(out + (size_t)(r + 8) * N_DIM + c) = v1;
        }
    }
}

// ------------------------------- host side --------------------------------
extern "C" void kernel_launch(void* const* d_in, const int* in_sizes, int n_in,
                              void* d_out, int out_size)
{
    const float* x = (const float*)d_in[0];
    const float* w = (const float*)d_in[1];
    float* out = (float*)d_out;

    void *xh_ptr = nullptr, *wbt_ptr = nullptr;
    cudaGetSymbolAddress(&xh_ptr, g_xh);
    cudaGetSymbolAddress(&wbt_ptr, g_wbt);

    {
        int n8 = (M_DIM * K_DIM) / 8;
        cvt_x_kernel<<<(n8 + 255) / 256, 256>>>((const float4*)x, (uint4*)xh_ptr, n8);
        dim3 gw(N_DIM / 64, K_DIM / 64);
        cvt_w_kernel<<<gw, 256>>>(w, (__half*)wbt_ptr);
    }

    // pad launch so ncu's "-s 5 -c 1" window lands on the GEMM
    prof_pad_kernel<<<1, 32>>>();

    cudaFuncSetAttribute(bgemm_mma_kernel,
                         cudaFuncAttributeMaxDynamicSharedMemorySize, SMEM_DYN);

    dim3 grid(M_DIM / BM, N_DIM / BN);  // (64, 16)
    bgemm_mma_kernel<<<grid, THREADS, SMEM_DYN>>>(
        (const __half*)xh_ptr, (const __half*)wbt_ptr, out);
}

// round 12
// speedup vs baseline: 1.4682x; 1.0087x over previous
#include <cuda_runtime.h>
#include <cuda_fp16.h>
#include <cstdint>

// ---------------------------------------------------------------------------
// out[8192,4096] = x[8192,4096]_fp32 @ sign(fp16(w[4096,4096]))
//
// R12: R11 GEMM (HMMA instruction wall ~699us) with warp-level barrier
// protocol: EMPTY arrives elected per-warp (count=16), all waits elected
// per-warp + __syncwarp reconvergence. Cuts mainloop barrier ops ~32x
// (-496 ATOMS, -992 try_wait polls per iter per CTA).
// Converts = R11 (vectorized).
// ---------------------------------------------------------------------------

#define M_DIM 8192
#define N_DIM 4096
#define K_DIM 4096

#define BM 128
#define BN 256
#define BK 64
#define STAGES 4
#define THREADS 512
#define NWARPS (THREADS / 32)
#define NKI (K_DIM / BK)   // 64

#define A_TILE_BYTES (BM * BK * 2)            // 16384
#define B_TILE_BYTES (BN * BK * 2)            // 32768
#define STAGE_BYTES  (A_TILE_BYTES + B_TILE_BYTES)   // 49152
#define SMEM_DYN     (1024 + 1024 + STAGES * STAGE_BYTES)  // 198656

// ------------------------------ scratch -----------------------------------
__device__ __align__(1024) __half g_xh[(size_t)M_DIM * K_DIM];   // 64 MB
__device__ __align__(1024) __half g_wbt[(size_t)N_DIM * K_DIM];  // 32 MB

// --------------------------- convert kernels -------------------------------
__global__ void __launch_bounds__(256, 8) cvt_x_kernel(
    const float4* __restrict__ x, uint4* __restrict__ xh, int n8)
{
    int i = blockIdx.x * blockDim.x + threadIdx.x;
    if (i >= n8) return;
    float4 v0 = x[i * 2];
    float4 v1 = x[i * 2 + 1];
    __half2 a = __floats2half2_rn(v0.x, v0.y);
    __half2 b = __floats2half2_rn(v0.z, v0.w);
    __half2 c = __floats2half2_rn(v1.x, v1.y);
    __half2 d = __floats2half2_rn(v1.z, v1.w);
    uint4 o;
    o.x = *reinterpret_cast<uint32_t*>(&a);
    o.y = *reinterpret_cast<uint32_t*>(&b);
    o.z = *reinterpret_cast<uint32_t*>(&c);
    o.w = *reinterpret_cast<uint32_t*>(&d);
    xh[i] = o;
}

// w[K,N] fp32 -> wbt[N,K] fp16 sign(fp16(w)); 64x64 tiles, vectorized IO
__global__ void __launch_bounds__(256, 4) cvt_w_kernel(
    const float* __restrict__ w, __half* __restrict__ wbt)
{
    __shared__ __half t[64][72];
    const int n0 = blockIdx.x * 64;
    const int k0 = blockIdx.y * 64;
    const int tid = threadIdx.x;

    const int lk = tid >> 4;
    const int ln = (tid & 15) << 2;
    #pragma unroll
    for (int i = 0; i < 4; i++) {
        int k = lk + i * 16;
        float4 v = *reinterpret_cast<const float4*>(
            w + (size_t)(k0 + k) * N_DIM + n0 + ln);
        float f[4] = {v.x, v.y, v.z, v.w};
        #pragma unroll
        for (int j = 0; j < 4; j++) {
            float hf = __half2float(__float2half_rn(f[j]));
            float s = (hf > 0.f) ? 1.f : ((hf < 0.f) ? -1.f : 0.f);
            t[ln + j][k] = __float2half_rn(s);
        }
    }
    __syncthreads();

    const int sn = tid >> 2;
    const int sk = (tid & 3) << 3;
    #pragma unroll
    for (int i = 0; i < 2; i++) {
        int kk = sk + i * 32;
        uint4 o = *reinterpret_cast<uint4*>(&t[sn][kk]);
        *reinterpret_cast<uint4*>(
            wbt + (size_t)(n0 + sn) * K_DIM + k0 + kk) = o;
    }
}

// dummy launch: keeps ncu's "-s 5 -c 1" window on the GEMM
__global__ void prof_pad_kernel() {}

// ------------------------------ PTX helpers -------------------------------
__device__ __forceinline__ uint32_t smem_u32(const void* p) {
    uint32_t a;
    asm("{ .reg .u64 t; cvta.to.shared.u64 t, %1; cvt.u32.u64 %0, t; }"
        : "=r"(a) : "l"(p));
    return a;
}

__device__ __forceinline__ uint32_t elect_one() {
    uint32_t pred;
    asm volatile(
        "{\n\t.reg .pred p;\n\t"
        "elect.sync _|p, 0xFFFFFFFF;\n\t"
        "selp.b32 %0, 1, 0, p;\n\t}"
        : "=r"(pred));
    return pred;
}

__device__ __forceinline__ void cp_async_16(uint32_t smem_dst, const void* gmem_src) {
    asm volatile("cp.async.cg.shared.global [%0], [%1], 16;"
                 :: "r"(smem_dst), "l"(gmem_src));
}

#define MBARRIER_INIT(addr, count) \
    asm volatile("mbarrier.init.shared.b64 [%0], %1;" \
                 :: "r"((uint32_t)(addr)), "r"((uint32_t)(count)) : "memory")

#define MBARRIER_ARRIVE(addr) \
    asm volatile("mbarrier.arrive.shared.b64 _, [%0];" \
                 :: "r"((uint32_t)(addr)) : "memory")

#define CPASYNC_MBAR_ARRIVE_NOINC(addr) \
    asm volatile("cp.async.mbarrier.arrive.noinc.shared.b64 [%0];" \
                 :: "r"((uint32_t)(addr)) : "memory")

#define MBARRIER_WAIT_PARITY(mbar_smem_addr, phase_parity) do { \
    uint32_t _mbar = (uint32_t)(mbar_smem_addr); \
    uint32_t _parity = (uint32_t)(phase_parity); \
    uint32_t _done; \
    asm volatile( \
        "{\n\t.reg .pred p;\n\t" \
        "mbarrier.try_wait.parity.acquire.cta.shared::cta.b64 p, [%1], %2;\n\t" \
        "selp.b32 %0, 1, 0, p;\n\t}" \
        : "=r"(_done) : "r"(_mbar), "r"(_parity) : "memory"); \
    if (!_done) { \
        asm volatile( \
            "{\n\t.reg .pred P1;\n\t" \
            "WAIT_LOOP_%=:\n\t" \
            "mbarrier.try_wait.parity.acquire.cta.shared::cta.b64 P1, [%0], %1, 0x989680;\n\t" \
            "@P1 bra.uni WAIT_DONE_%=;\n\t" \
            "bra.uni WAIT_LOOP_%=;\n\t" \
            "WAIT_DONE_%=:\n\t}" \
            :: "r"(_mbar), "r"(_parity) : "memory"); \
    } \
} while(0)

// elected single-lane wait + warp reconvergence (mbarrier phase flip is
// CTA-visible; __syncwarp orders subsequent reads/writes of other lanes)
#define WARP_WAIT_PARITY(addr, parity) do { \
    if (elect_one()) { MBARRIER_WAIT_PARITY(addr, parity); } \
    __syncwarp(); \
} while (0)

__device__ __forceinline__ void ldmatrix_x4(uint32_t& r0, uint32_t& r1,
                                            uint32_t& r2, uint32_t& r3, uint32_t addr) {
    asm volatile("ldmatrix.sync.aligned.m8n8.x4.shared.b16 {%0,%1,%2,%3}, [%4];"
                 : "=r"(r0), "=r"(r1), "=r"(r2), "=r"(r3) : "r"(addr));
}

__device__ __forceinline__ void mma_16816(float* c, const uint32_t* a, const uint32_t* b) {
    asm volatile(
        "mma.sync.aligned.m16n8k16.row.col.f32.f16.f16.f32 "
        "{%0,%1,%2,%3}, {%4,%5,%6,%7}, {%8,%9}, {%0,%1,%2,%3};"
        : "+f"(c[0]), "+f"(c[1]), "+f"(c[2]), "+f"(c[3])
        : "r"(a[0]), "r"(a[1]), "r"(a[2]), "r"(a[3]), "r"(b[0]), "r"(b[1]));
}

// swizzle within a [rows][BK] fp16 tile, 128B rows: 16B chunk XOR (row & 7)
__device__ __forceinline__ uint32_t tile_off(int row, int chunk) {
    return (uint32_t)(row * 128 + ((chunk ^ (row & 7)) << 4));
}

// ------------------------------ GEMM kernel --------------------------------
__global__ void __launch_bounds__(THREADS, 1) bgemm_mma_kernel(
    const __half* __restrict__ A,   // [M,K]
    const __half* __restrict__ B,   // [N,K]
    float* __restrict__ out)
{
    extern __shared__ uint8_t smem_raw[];
    uint32_t raw = smem_u32(smem_raw);
    const uint32_t hdr   = (raw + 1023u) & ~1023u;
    const uint32_t tiles = hdr + 1024u;

    #define FULL_BAR(s)  (hdr + (uint32_t)(s) * 8u)
    #define EMPTY_BAR(s) (hdr + 64u + (uint32_t)(s) * 8u)

    const int tid  = threadIdx.x;
    const int wid  = tid >> 5;
    const int lane = tid & 31;
    const int m0 = blockIdx.x * BM;
    const int n0 = blockIdx.y * BN;

    const int warp_m = wid & 3;   // 4 warps over M: 32 rows each
    const int warp_n = wid >> 2;  // 4 warps over N: 64 cols each

    const int ld_row0  = tid >> 3;   // 0..63
    const int ld_chunk = tid & 7;    // 0..7

    auto load_stage = [&](int slot, int kt) {
        const uint32_t sA = tiles + slot * STAGE_BYTES;
        const uint32_t sB = sA + A_TILE_BYTES;
        const int kcol = kt * BK + ld_chunk * 8;
        #pragma unroll
        for (int p = 0; p < 2; p++) {
            int row = ld_row0 + p * 64;
            cp_async_16(sA + tile_off(row, ld_chunk),
                        A + (size_t)(m0 + row) * K_DIM + kcol);
        }
        #pragma unroll
        for (int p = 0; p < 4; p++) {
            int row = ld_row0 + p * 64;
            cp_async_16(sB + tile_off(row, ld_chunk),
                        B + (size_t)(n0 + row) * K_DIM + kcol);
        }
        CPASYNC_MBAR_ARRIVE_NOINC(FULL_BAR(slot));
    };

    if (tid == 0) {
        #pragma unroll
        for (int s = 0; s < STAGES; s++) {
            MBARRIER_INIT(FULL_BAR(s), THREADS);   // per-thread noinc arrives
            MBARRIER_INIT(EMPTY_BAR(s), NWARPS);   // per-warp elected arrives
        }
        asm volatile("fence.proxy.async.shared::cta;" ::: "memory");
    }
    __syncthreads();

    const int lrow = lane & 15;
    const int lsel = lane >> 4;

    uint32_t a_off[2], b_off[4];
    #pragma unroll
    for (int mi = 0; mi < 2; mi++)
        a_off[mi] = tile_off(warp_m * 32 + mi * 16 + lrow, lsel);
    #pragma unroll
    for (int nj = 0; nj < 4; nj++)
        b_off[nj] = tile_off(warp_n * 64 + nj * 16 + lrow, lsel);

    float acc[2][8][4];
    #pragma unroll
    for (int mi = 0; mi < 2; mi++)
        #pragma unroll
        for (int ni = 0; ni < 8; ni++)
            #pragma unroll
            for (int j = 0; j < 4; j++) acc[mi][ni][j] = 0.f;

    // prologue: fill stages 0..2 (EMPTY parity-1 waits pass immediately)
    #pragma unroll
    for (int s = 0; s < STAGES - 1; s++) {
        WARP_WAIT_PARITY(EMPTY_BAR(s), 1);
        load_stage(s, s);
    }

    for (int it = 0; it < NKI; it++) {
        const int s = it & 3;
        const uint32_t sA = tiles + s * STAGE_BYTES;
        const uint32_t sB = sA + A_TILE_BYTES;

        // consumer: elected wait for stage it full
        WARP_WAIT_PARITY(FULL_BAR(s), (it >> 2) & 1);

        #pragma unroll
        for (int kk = 0; kk < BK / 16; kk++) {
            const uint32_t kx = (uint32_t)kk << 5;

            uint32_t a[2][4];
            #pragma unroll
            for (int mi = 0; mi < 2; mi++)
                ldmatrix_x4(a[mi][0], a[mi][1], a[mi][2], a[mi][3],
                            (sA + a_off[mi]) ^ kx);
            uint32_t b[8][2];
            #pragma unroll
            for (int nj = 0; nj < 4; nj++) {
                uint32_t r0, r1, r2, r3;
                ldmatrix_x4(r0, r1, r2, r3, (sB + b_off[nj]) ^ kx);
                b[nj * 2 + 0][0] = r0; b[nj * 2 + 1][0] = r1;
                b[nj * 2 + 0][1] = r2; b[nj * 2 + 1][1] = r3;
            }

            // release the stage after this warp's LAST smem read of it:
            // syncwarp orders all lanes' ldmatrix, elected lane arrives
            if (kk == BK / 16 - 1) {
                __syncwarp();
                if (elect_one()) MBARRIER_ARRIVE(EMPTY_BAR(s));
            }

            #pragma unroll
            for (int mi = 0; mi < 2; mi++)
                #pragma unroll
                for (int ni = 0; ni < 8; ni++)
                    mma_16816(acc[mi][ni], a[mi], b[ni]);
        }

        // producer: refill stage it+3
        const int kt = it + STAGES - 1;
        if (kt < NKI) {
            const int ps = kt & 3;
            WARP_WAIT_PARITY(EMPTY_BAR(ps), ((kt >> 2) & 1) ^ 1);
            load_stage(ps, kt);
        }
    }

    // ------------------------------ epilogue -------------------------------
    const int tq = lane >> 2;
    const int tp = lane & 3;
    #pragma unroll
    for (int mi = 0; mi < 2; mi++) {
        #pragma unroll
        for (int ni = 0; ni < 8; ni++) {
            int r = m0 + warp_m * 32 + mi * 16 + tq;
            int c = n0 + warp_n * 64 + ni * 8 + tp * 2;
            float2 v0 = make_float2(acc[mi][ni][0], acc[mi][ni][1]);
            float2 v1 = make_float2(acc[mi][ni][2], acc[mi][ni][3]);
            *reinterpret_cast<float2*>(out + (size_t)r * N_DIM + c) = v0;
            *reinterpret_cast<float2*>(out + (size_t)(r + 8) * N_DIM + c) = v1;
        }
    }
}

// ------------------------------- host side --------------------------------
extern "C" void kernel_launch(void* const* d_in, const int* in_sizes, int n_in,
                              void* d_out, int out_size)
{
    const float* x = (const float*)d_in[0];
    const float* w = (const float*)d_in[1];
    float* out = (float*)d_out;

    void *xh_ptr = nullptr, *wbt_ptr = nullptr;
    cudaGetSymbolAddress(&xh_ptr, g_xh);
    cudaGetSymbolAddress(&wbt_ptr, g_wbt);

    {
        int n8 = (M_DIM * K_DIM) / 8;
        cvt_x_kernel<<<(n8 + 255) / 256, 256>>>((const float4*)x, (uint4*)xh_ptr, n8);
        dim3 gw(N_DIM / 64, K_DIM / 64);
        cvt_w_kernel<<<gw, 256>>>(w, (__half*)wbt_ptr);
    }

    // pad launch so ncu's "-s 5 -c 1" window lands on the GEMM
    prof_pad_kernel<<<1, 32>>>();

    cudaFuncSetAttribute(bgemm_mma_kernel,
                         cudaFuncAttributeMaxDynamicSharedMemorySize, SMEM_DYN);

    dim3 grid(M_DIM / BM, N_DIM / BN);  // (64, 16)
    bgemm_mma_kernel<<<grid, THREADS, SMEM_DYN>>>(
        (const __half*)xh_ptr, (const __half*)wbt_ptr, out);
}